// round 5
// baseline (speedup 1.0000x reference)
#include <cuda_runtime.h>
#include <math.h>

#define NN 50000
#define NE 600000
#define FEATS 128
#define WSH_STRIDE 132
#define TILE_N 64
#define RPW 8
#define ESH_CAP 2048

// smem: Wsh[128][132] + Ash[64][128] + Esh[2048] + Osh[72]
#define SMEM_BYTES ((128 * WSH_STRIDE + TILE_N * FEATS) * 4 + ESH_CAP * 4 + 72 * 4)

// -------------------- device scratch ---------------------------------------
// Barrier state isolated in its own 128B lines (avoid false L1 sharing).
__device__ __align__(128) unsigned g_gen;
__device__ __align__(128) unsigned g_cnt;
__device__ __align__(128) int g_idx64;
__device__ __align__(128) int g_count[NN];
__device__ int g_off[NN + 1];
__device__ int g_cursor[NN];
__device__ __align__(128) int g_btot[512];
__device__ int g_edges[NE];

// packed fp32x2 FMA (sm_103a; ptxas never auto-emits this)
#define FFMA2(d, a, b) \
    asm("fma.rn.f32x2 %0, %1, %2, %0;" : "+l"(d) : "l"(a), "l"(b))
#define PACKDUP(d, x) \
    asm("mov.b64 %0, {%1, %1};" : "=l"(d) : "r"(__float_as_uint(x)))

// -------------------- grid barrier ------------------------------------------
__device__ __forceinline__ void gbar(unsigned& lg) {
    __syncthreads();
    if (threadIdx.x == 0) {
        __threadfence();
        unsigned arr = atomicAdd(&g_cnt, 1u);
        if (arr == gridDim.x - 1) {
            g_cnt = 0;
            __threadfence();
            *(volatile unsigned*)&g_gen = lg + 1;
        } else {
            while (*(volatile unsigned*)&g_gen == lg) { __nanosleep(64); }
        }
        __threadfence();
    }
    __syncthreads();
    lg++;
}

// ---------------------------------------------------------------------------
// One persistent kernel: CSR build + fused gather/GEMM/tanh.
// ---------------------------------------------------------------------------
__global__ __launch_bounds__(256, 2) void gcn_mega_kernel(
    const float* __restrict__ feat, const float* __restrict__ W,
    const float* __restrict__ b, const void* __restrict__ src,
    const void* __restrict__ dst, float* __restrict__ out,
    int nE, int nNodes) {
    extern __shared__ float sh[];
    float* Wsh = sh;                                  // [128][132]
    float* Ash = sh + 128 * WSH_STRIDE;               // [64][128]
    int*   Esh = (int*)(Ash + TILE_N * FEATS);        // [2048] (also scan scratch)
    int*   Osh = Esh + ESH_CAP;                       // [72]

    int tid = threadIdx.x;
    int lane = tid & 31;
    int warp = tid >> 5;
    int nth = gridDim.x * 256;
    int gt = blockIdx.x * 256 + tid;

    unsigned lg = *(volatile unsigned*)&g_gen;

    // ===== Phase A: detect idx dtype, zero counts, stage W into smem =====
    if (blockIdx.x == 0 && tid == 0) {
        const long long* p = (const long long*)src;
        int is64 = 1;
        for (int k = 0; k < 64; k++) {
            long long v = p[k];
            if (v < 0 || v >= NN) { is64 = 0; break; }
        }
        g_idx64 = is64;
    }
    for (int i = gt; i < NN; i += nth) g_count[i] = 0;
    for (int idx = tid; idx < 128 * 128; idx += 256) {
        int j = idx >> 7;
        int k = idx & 127;
        Wsh[k * WSH_STRIDE + j] = W[idx];   // W transposed
    }
    gbar(lg);

    // ===== Phase B: histogram of dst =====
    int idx64 = __ldcg(&g_idx64);
    if (idx64) {
        const long long* p = (const long long*)dst;
        for (int i = gt; i < nE; i += nth) atomicAdd(&g_count[(int)p[i]], 1);
    } else {
        const int* p = (const int*)dst;
        for (int i = gt; i < nE; i += nth) atomicAdd(&g_count[p[i]], 1);
    }
    gbar(lg);

    // ===== Phase C: per-block-range exclusive scan (chunks of 256, carry) ===
    int per = ((NN + gridDim.x - 1) / gridDim.x + 255) & ~255;
    int rbeg = blockIdx.x * per;
    {
        int* wsum = Esh;   // scratch: 9 ints
        int carry = 0;
        for (int base = rbeg; base < rbeg + per; base += 256) {
            int gid = base + tid;
            int v = (gid < NN) ? __ldcg(&g_count[gid]) : 0;
            int x = v;
            #pragma unroll
            for (int o = 1; o < 32; o <<= 1) {
                int y = __shfl_up_sync(0xffffffff, x, o);
                if (lane >= o) x += y;
            }
            if (lane == 31) wsum[warp] = x;
            __syncthreads();
            if (tid == 0) {
                int run = 0;
                #pragma unroll
                for (int i = 0; i < 8; i++) { int t = wsum[i]; wsum[i] = run; run += t; }
                wsum[8] = run;
            }
            __syncthreads();
            int excl = x - v + wsum[warp] + carry;
            if (gid < NN) g_off[gid] = excl;
            carry += wsum[8];
            __syncthreads();   // protect wsum before next chunk overwrites it
        }
        if (tid == 0) g_btot[blockIdx.x] = carry;
    }
    gbar(lg);

    // ===== Phase D: add inter-block prefix, publish offsets + cursors ======
    {
        int* Ssh = Esh;   // scratch: 256 ints
        int pre = 0;
        for (int t = tid; t < (int)blockIdx.x; t += 256) pre += __ldcg(&g_btot[t]);
        Ssh[tid] = pre;
        __syncthreads();
        for (int o = 128; o > 0; o >>= 1) {
            if (tid < o) Ssh[tid] += Ssh[tid + o];
            __syncthreads();
        }
        int add = Ssh[0];
        for (int base = rbeg; base < rbeg + per; base += 256) {
            int gid = base + tid;
            if (gid < NN) {
                int o = g_off[gid] + add;   // own block's writes: coherent
                g_off[gid] = o;
                g_cursor[gid] = o;
            }
        }
        if (blockIdx.x == 0 && tid == 0) g_off[NN] = nE;
    }
    gbar(lg);

    // ===== Phase E: fill edge lists =====
    if (idx64) {
        const long long* ps = (const long long*)src;
        const long long* pd = (const long long*)dst;
        for (int i = gt; i < nE; i += nth) {
            int d = (int)pd[i], s = (int)ps[i];
            int pos = atomicAdd(&g_cursor[d], 1);
            g_edges[pos] = s;
        }
    } else {
        const int* ps = (const int*)src;
        const int* pd = (const int*)dst;
        for (int i = gt; i < nE; i += nth) {
            int d = pd[i], s = ps[i];
            int pos = atomicAdd(&g_cursor[d], 1);
            g_edges[pos] = s;
        }
    }
    gbar(lg);

    // ===== Phase F: fused gather + GEMM + bias + tanh =====
    int j0 = lane * 4;
    int lane4 = lane * 4;
    float4 bias = *(const float4*)(b + j0);

    for (int tile = blockIdx.x * TILE_N; tile < nNodes; tile += gridDim.x * TILE_N) {
        __syncthreads();   // Ash/Esh reuse

        int tend = tile + TILE_N;
        if (tend > nNodes) tend = nNodes;
        int e0t = __ldcg(&g_off[tile]);
        int e1t = __ldcg(&g_off[tend]);
        int cnt = e1t - e0t;
        bool staged = (cnt <= ESH_CAP);
        if (tid <= TILE_N) {
            int nd = tile + tid;
            if (nd > nNodes) nd = nNodes;
            Osh[tid] = __ldcg(&g_off[nd]);
        }
        if (staged) {
            for (int i = tid; i < cnt; i += 256) Esh[i] = __ldcg(&g_edges[e0t + i]);
        }
        __syncthreads();

        float4 acc[RPW];
        #pragma unroll
        for (int r = 0; r < RPW; r++) acc[r] = make_float4(0.f, 0.f, 0.f, 0.f);

        if (staged) {
            #pragma unroll
            for (int r = 0; r < RPW; r++) {
                int node = tile + warp * RPW + r;
                if (node < nNodes) {
                    int eb = Osh[warp * RPW + r] - e0t;
                    int ee = Osh[warp * RPW + r + 1] - e0t;
                    for (int e = eb; e < ee; e += 8) {
                        #pragma unroll
                        for (int u = 0; u < 8; u++) {
                            int j = e + u;
                            int s = Esh[j < ee ? j : eb];
                            float4 f = *(const float4*)(feat + (long)s * FEATS + lane4);
                            if (j < ee) {
                                acc[r].x += f.x; acc[r].y += f.y;
                                acc[r].z += f.z; acc[r].w += f.w;
                            }
                        }
                    }
                }
            }
        } else {
            const int* gp = g_edges + e0t;
            #pragma unroll
            for (int r = 0; r < RPW; r++) {
                int node = tile + warp * RPW + r;
                if (node < nNodes) {
                    int eb = Osh[warp * RPW + r] - e0t;
                    int ee = Osh[warp * RPW + r + 1] - e0t;
                    for (int e = eb; e < ee; e += 8) {
                        #pragma unroll
                        for (int u = 0; u < 8; u++) {
                            int j = e + u;
                            int s = __ldcg(&gp[j < ee ? j : eb]);
                            float4 f = *(const float4*)(feat + (long)s * FEATS + lane4);
                            if (j < ee) {
                                acc[r].x += f.x; acc[r].y += f.y;
                                acc[r].z += f.z; acc[r].w += f.w;
                            }
                        }
                    }
                }
            }
        }

        #pragma unroll
        for (int r = 0; r < RPW; r++)
            *(float4*)(Ash + (warp * RPW + r) * FEATS + lane4) = acc[r];
        __syncthreads();

        // GEMM: 8 rows x 4 cols per lane, packed f32x2 FMA
        const float* abase = Ash + warp * RPW * FEATS;
        unsigned long long c[2 * RPW];
        #pragma unroll
        for (int r = 0; r < 2 * RPW; r++) c[r] = 0;

        #pragma unroll 2
        for (int k4 = 0; k4 < FEATS; k4 += 4) {
            float4 xv[RPW];
            #pragma unroll
            for (int r = 0; r < RPW; r++)
                xv[r] = *(const float4*)(abase + r * FEATS + k4);
            #pragma unroll
            for (int kk = 0; kk < 4; kk++) {
                ulonglong2 wv =
                    *(const ulonglong2*)(Wsh + (k4 + kk) * WSH_STRIDE + j0);
                #pragma unroll
                for (int r = 0; r < RPW; r++) {
                    unsigned long long d;
                    PACKDUP(d, ((const float*)&xv[r])[kk]);
                    FFMA2(c[2 * r], wv.x, d);
                    FFMA2(c[2 * r + 1], wv.y, d);
                }
            }
        }

        int nbase = tile + warp * RPW;
        #pragma unroll
        for (int r = 0; r < RPW; r++) {
            if (nbase + r < nNodes) {
                float2 lo = *(float2*)&c[2 * r];
                float2 hi = *(float2*)&c[2 * r + 1];
                float4 o;
                o.x = tanhf(lo.x + bias.x);
                o.y = tanhf(lo.y + bias.y);
                o.z = tanhf(hi.x + bias.z);
                o.w = tanhf(hi.y + bias.w);
                *(float4*)(out + (long)(nbase + r) * FEATS + j0) = o;
            }
        }
    }
}

// ---------------------------------------------------------------------------
extern "C" void kernel_launch(void* const* d_in, const int* in_sizes, int n_in,
                              void* d_out, int out_size) {
    const float* feature = (const float*)d_in[0];
    const float* W       = (const float*)d_in[1];
    const float* b       = (const float*)d_in[2];
    const void*  src     = d_in[3];
    const void*  dst     = d_in[4];
    float* out = (float*)d_out;

    int nEdges = in_sizes[3];
    int nNodes = out_size / FEATS;

    cudaFuncSetAttribute(gcn_mega_kernel,
                         cudaFuncAttributeMaxDynamicSharedMemorySize, SMEM_BYTES);

    // Deadlock-safe persistent grid: SMs x achievable occupancy (<= 2).
    int smcount = 148, maxb = 1;
    cudaDeviceGetAttribute(&smcount, cudaDevAttrMultiProcessorCount, 0);
    cudaOccupancyMaxActiveBlocksPerMultiprocessor(&maxb, gcn_mega_kernel,
                                                  256, SMEM_BYTES);
    if (maxb < 1) maxb = 1;
    if (maxb > 2) maxb = 2;
    int blocks = smcount * maxb;
    if (blocks > 512) blocks = 512;   // g_btot capacity

    gcn_mega_kernel<<<blocks, 256, SMEM_BYTES>>>(feature, W, b, src, dst, out,
                                                 nEdges, nNodes);
}